// round 1
// baseline (speedup 1.0000x reference)
#include <cuda_runtime.h>
#include <math.h>

#define B_ 1024
#define N_ 128
#define D_ 512

// ---- output layout (float32, concatenated in reference return order) ----
__device__ __host__ constexpr size_t KD_ = (size_t)B_ * N_ * D_;   // 67108864
__device__ __host__ constexpr size_t O1_ = KD_;                    // updated_values
__device__ __host__ constexpr size_t O2_ = 2 * KD_;                // updated_protection (B*N)
__device__ __host__ constexpr size_t O3_ = O2_ + (size_t)B_ * N_;  // write_strength (B)
__device__ __host__ constexpr size_t O4_ = O3_ + B_;               // merge_preference (B)
__device__ __host__ constexpr size_t O5_ = O4_ + B_;               // binding_strength (B)
__device__ __host__ constexpr size_t O6_ = O5_ + B_;               // overwrite.mean (B)
__device__ __host__ constexpr size_t O7_ = O6_ + B_;               // updated_protection.mean (B)
__device__ __host__ constexpr size_t O8_ = O7_ + B_;               // max_similarity (B)
__device__ __host__ constexpr size_t O9_ = O8_ + B_;               // overwrite (B*N)

// ---- scratch (__device__ globals; no allocations allowed) ----
__device__ float g_ck[B_ * D_];     // candidate_key (tanh)
__device__ float g_cv[B_ * D_];     // candidate_value (tanh)
__device__ float g_sim[B_ * N_];
__device__ float g_occ[B_ * N_];
__device__ float g_lprot[B_ * N_];
__device__ float g_ws[B_];
__device__ float g_im[B_];
__device__ float g_hmg[B_];
__device__ float g_hbd[B_];
__device__ float g_invnc[B_];
__device__ int   g_tgt[B_];
__device__ float g_owt[B_];
__device__ float g_km[B_];
__device__ float g_vm[B_];

__device__ __forceinline__ float sigm(float x) { return 1.0f / (1.0f + expf(-x)); }
__device__ __forceinline__ float clip01(float x) { return fminf(fmaxf(x, 0.0f), 1.0f); }

// =====================================================================
// Kernel 1: candidate key/value GEMM + tanh.
// grid (B/8, 2), block 128. Each block: 8 batches x 512 cols.
// Each thread: 4 cols (tid, tid+128, tid+256, tid+384) for 8 batches.
// =====================================================================
__global__ void __launch_bounds__(128) k_gemm(
    const float* __restrict__ hidden,
    const float* __restrict__ Wk, const float* __restrict__ bk,
    const float* __restrict__ Wv, const float* __restrict__ bv)
{
    __shared__ __align__(16) float ht[D_][12];  // transposed hidden tile, padded rows

    const int tid = threadIdx.x;
    const int b0 = blockIdx.x * 8;
    const float* __restrict__ W    = blockIdx.y ? Wv : Wk;
    const float* __restrict__ bias = blockIdx.y ? bv : bk;
    float* outp = blockIdx.y ? g_cv : g_ck;

    // fill transposed tile: 8 batches x 512 d
    for (int i = tid; i < 8 * 128; i += 128) {
        int bb = i >> 7;
        int d4 = i & 127;
        float4 v = reinterpret_cast<const float4*>(hidden + (size_t)(b0 + bb) * D_)[d4];
        ht[4 * d4 + 0][bb] = v.x;
        ht[4 * d4 + 1][bb] = v.y;
        ht[4 * d4 + 2][bb] = v.z;
        ht[4 * d4 + 3][bb] = v.w;
    }
    __syncthreads();

    float acc[8][4];
#pragma unroll
    for (int i = 0; i < 8; i++)
#pragma unroll
        for (int j = 0; j < 4; j++) acc[i][j] = 0.0f;

#pragma unroll 4
    for (int d = 0; d < D_; d++) {
        const float* wr = W + (size_t)d * D_;
        float w0 = __ldg(wr + tid);
        float w1 = __ldg(wr + tid + 128);
        float w2 = __ldg(wr + tid + 256);
        float w3 = __ldg(wr + tid + 384);
        float4 ha = *reinterpret_cast<const float4*>(&ht[d][0]);
        float4 hb = *reinterpret_cast<const float4*>(&ht[d][4]);
        float h[8] = {ha.x, ha.y, ha.z, ha.w, hb.x, hb.y, hb.z, hb.w};
#pragma unroll
        for (int bb = 0; bb < 8; bb++) {
            acc[bb][0] += h[bb] * w0;
            acc[bb][1] += h[bb] * w1;
            acc[bb][2] += h[bb] * w2;
            acc[bb][3] += h[bb] * w3;
        }
    }

    float b0v = bias[tid];
    float b1v = bias[tid + 128];
    float b2v = bias[tid + 256];
    float b3v = bias[tid + 384];
#pragma unroll
    for (int bb = 0; bb < 8; bb++) {
        float* orow = outp + (size_t)(b0 + bb) * D_;
        orow[tid]       = tanhf(acc[bb][0] + b0v);
        orow[tid + 128] = tanhf(acc[bb][1] + b1v);
        orow[tid + 256] = tanhf(acc[bb][2] + b2v);
        orow[tid + 384] = tanhf(acc[bb][3] + b3v);
    }
}

// =====================================================================
// Kernel 2: per-batch scalar heads + ||candidate_key||.
// grid B, block 128 (float4 per thread).
// =====================================================================
__global__ void __launch_bounds__(128) k_heads(
    const float* __restrict__ hidden,
    const float* __restrict__ Wwr, const float* __restrict__ bwr,
    const float* __restrict__ Wmg, const float* __restrict__ bmg,
    const float* __restrict__ Wbd, const float* __restrict__ bbd,
    const float* __restrict__ Wim, const float* __restrict__ bim,
    float* __restrict__ out)
{
    const int b = blockIdx.x;
    const int t = threadIdx.x;
    float4 h = reinterpret_cast<const float4*>(hidden + (size_t)b * D_)[t];
    float4 c = reinterpret_cast<const float4*>(g_ck + (size_t)b * D_)[t];

    float4 w;
    w = reinterpret_cast<const float4*>(Wwr)[t];
    float pwr = h.x * w.x + h.y * w.y + h.z * w.z + h.w * w.w;
    w = reinterpret_cast<const float4*>(Wmg)[t];
    float pmg = h.x * w.x + h.y * w.y + h.z * w.z + h.w * w.w;
    w = reinterpret_cast<const float4*>(Wbd)[t];
    float pbd = h.x * w.x + h.y * w.y + h.z * w.z + h.w * w.w;
    w = reinterpret_cast<const float4*>(Wim)[t];
    float pim = h.x * w.x + h.y * w.y + h.z * w.z + h.w * w.w;
    float pss = c.x * c.x + c.y * c.y + c.z * c.z + c.w * c.w;

#pragma unroll
    for (int o = 16; o; o >>= 1) {
        pwr += __shfl_xor_sync(0xffffffffu, pwr, o);
        pmg += __shfl_xor_sync(0xffffffffu, pmg, o);
        pbd += __shfl_xor_sync(0xffffffffu, pbd, o);
        pim += __shfl_xor_sync(0xffffffffu, pim, o);
        pss += __shfl_xor_sync(0xffffffffu, pss, o);
    }
    __shared__ float red[4][5];
    if ((t & 31) == 0) {
        int wi = t >> 5;
        red[wi][0] = pwr; red[wi][1] = pmg; red[wi][2] = pbd;
        red[wi][3] = pim; red[wi][4] = pss;
    }
    __syncthreads();
    if (t == 0) {
        float dwr = red[0][0] + red[1][0] + red[2][0] + red[3][0];
        float dmg = red[0][1] + red[1][1] + red[2][1] + red[3][1];
        float dbd = red[0][2] + red[1][2] + red[2][2] + red[3][2];
        float dIm = red[0][3] + red[1][3] + red[2][3] + red[3][3];
        float dss = red[0][4] + red[1][4] + red[2][4] + red[3][4];
        float ws = sigm(dwr + bwr[0]);
        g_ws[b] = ws;
        out[O3_ + b] = ws;
        g_im[b] = sigm(dIm + bim[0]);
        g_hmg[b] = dmg + bmg[0];
        g_hbd[b] = dbd + bbd[0];
        g_invnc[b] = 1.0f / fmaxf(sqrtf(dss), 1e-6f);
    }
}

// =====================================================================
// Kernel 3: the streaming pass. One block per (b,n):
//   threads 0..127  : key row   -> dot(cand,key), ||key||^2, copy to out
//   threads 128..255: value row -> ||v||^2, v@Woc, v@Wpr,  copy to out
// =====================================================================
__global__ void __launch_bounds__(256) k_score(
    const float* __restrict__ wkeys, const float* __restrict__ wvals,
    const float* __restrict__ Woc, const float* __restrict__ boc,
    const float* __restrict__ Wpr, const float* __restrict__ bpr,
    float* __restrict__ out)
{
    const int blk = blockIdx.x;
    const int b = blk >> 7;
    const int tid = threadIdx.x;
    const size_t rowoff = (size_t)blk * D_;

    float p0 = 0.0f, p1 = 0.0f, p2 = 0.0f;
    if (tid < 128) {
        float4 k = reinterpret_cast<const float4*>(wkeys + rowoff)[tid];
        float4 c = reinterpret_cast<const float4*>(g_ck + (size_t)b * D_)[tid];
        reinterpret_cast<float4*>(out + rowoff)[tid] = k;  // updated_keys copy
        p0 = k.x * c.x + k.y * c.y + k.z * c.z + k.w * c.w;
        p1 = k.x * k.x + k.y * k.y + k.z * k.z + k.w * k.w;
    } else {
        int i = tid - 128;
        float4 v = reinterpret_cast<const float4*>(wvals + rowoff)[i];
        reinterpret_cast<float4*>(out + O1_ + rowoff)[i] = v;  // updated_values copy
        float4 wo = reinterpret_cast<const float4*>(Woc)[i];
        float4 wp = reinterpret_cast<const float4*>(Wpr)[i];
        p0 = v.x * v.x + v.y * v.y + v.z * v.z + v.w * v.w;
        p1 = v.x * wo.x + v.y * wo.y + v.z * wo.z + v.w * wo.w;
        p2 = v.x * wp.x + v.y * wp.y + v.z * wp.z + v.w * wp.w;
    }
#pragma unroll
    for (int o = 16; o; o >>= 1) {
        p0 += __shfl_xor_sync(0xffffffffu, p0, o);
        p1 += __shfl_xor_sync(0xffffffffu, p1, o);
        p2 += __shfl_xor_sync(0xffffffffu, p2, o);
    }
    __shared__ float red[8][3];
    if ((tid & 31) == 0) {
        int w = tid >> 5;
        red[w][0] = p0; red[w][1] = p1; red[w][2] = p2;
    }
    __syncthreads();
    if (tid == 0) {
        float dot_ck = red[0][0] + red[1][0] + red[2][0] + red[3][0];
        float ss_k   = red[0][1] + red[1][1] + red[2][1] + red[3][1];
        float ss_v   = red[4][0] + red[5][0] + red[6][0] + red[7][0];
        float dvoc   = red[4][1] + red[5][1] + red[6][1] + red[7][1];
        float dvpr   = red[4][2] + red[5][2] + red[6][2] + red[7][2];

        float sim = dot_ck * g_invnc[b] / fmaxf(sqrtf(ss_k), 1e-6f);
        float nocc = clip01(sqrtf(ss_v) * 0.04419417382415922f);  // / sqrt(512)
        float locc = sigm(dvoc + boc[0]);
        float occ = clip01(0.5f * locc + 0.5f * nocc);
        float lprot = sigm(dvpr + bpr[0]);
        g_sim[blk] = sim;
        g_occ[blk] = occ;
        g_lprot[blk] = lprot;
    }
}

// =====================================================================
// Kernel 4: per-batch selection + all small outputs.
// grid B, block 128 (one thread per slot n).
// =====================================================================
__global__ void __launch_bounds__(128) k_select(
    const float* __restrict__ wprot, const float* __restrict__ wusage,
    const float* __restrict__ wage, float* __restrict__ out)
{
    const int b = blockIdx.x;
    const int n = threadIdx.x;
    const int idx = b * N_ + n;

    float sim = g_sim[idx];
    float occ = g_occ[idx];
    float lp  = g_lprot[idx];
    float wp  = wprot[idx];
    float ep = clip01(0.4f * lp + 0.6f * wp);
    float eu = clip01(0.5f * occ + 0.5f * wusage[idx]);
    float ea = clip01(wage[idx]);
    float rs = 1.15f * (1.0f - occ) + 0.85f * (1.0f - ep) + 0.65f * ea
             + 0.45f * (1.0f - eu) + 0.25f * (1.0f - sim);

    __shared__ float sS[N_], sO[N_], sU[N_], sA[N_], sE[N_];
    sS[n] = sim; sO[n] = occ; sU[n] = eu; sA[n] = ea; sE[n] = ep;

    // two argmaxes (first-index tie break, matching jnp.argmax)
    float v1 = sim; int i1 = n;
    float v2 = rs;  int i2 = n;
#pragma unroll
    for (int o = 16; o; o >>= 1) {
        float ov = __shfl_down_sync(0xffffffffu, v1, o);
        int   oi = __shfl_down_sync(0xffffffffu, i1, o);
        if (ov > v1 || (ov == v1 && oi < i1)) { v1 = ov; i1 = oi; }
        ov = __shfl_down_sync(0xffffffffu, v2, o);
        oi = __shfl_down_sync(0xffffffffu, i2, o);
        if (ov > v2 || (ov == v2 && oi < i2)) { v2 = ov; i2 = oi; }
    }
    __shared__ float wv1[4], wv2[4];
    __shared__ int wi1[4], wi2[4];
    if ((n & 31) == 0) {
        int w = n >> 5;
        wv1[w] = v1; wi1[w] = i1; wv2[w] = v2; wi2[w] = i2;
    }
    __syncthreads();

    __shared__ int sh_tgt;
    __shared__ float sh_owt, sh_bf;
    if (n == 0) {
        float bv = wv1[0]; int bi = wi1[0];
#pragma unroll
        for (int w = 1; w < 4; w++)
            if (wv1[w] > bv || (wv1[w] == bv && wi1[w] < bi)) { bv = wv1[w]; bi = wi1[w]; }
        int mi = bi;
        float rbv = wv2[0]; int ri = wi2[0];
#pragma unroll
        for (int w = 1; w < 4; w++)
            if (wv2[w] > rbv || (wv2[w] == rbv && wi2[w] < ri)) { rbv = wv2[w]; ri = wi2[w]; }

        float ms = sS[mi], mo = sO[mi], mu = sU[mi], ma = sA[mi];
        float mp = sigm(g_hmg[b] + 2.4f * ms + 1.6f * (mo - 0.5f)
                        + 1.0f * (mu - 0.5f) - 0.8f * ma);
        bool um = (mp >= 0.5f) && (ms > 0.55f) && (mo > 0.35f);
        int tgt = um ? mi : ri;
        float bind = sigm(g_hbd[b] + 2.2f * ms);
        float conflict = clip01(1.0f - sS[tgt]);
        float owt = (0.15f + 0.85f * g_ws[b]) * (1.0f - 0.65f * sE[tgt] * conflict);
        float im = g_im[b];

        out[O4_ + b] = mp;
        out[O5_ + b] = bind;
        out[O6_ + b] = owt * (1.0f / N_);
        out[O8_ + b] = ms;
        g_tgt[b] = tgt;
        g_owt[b] = owt;
        g_km[b] = um ? (0.22f + 0.38f * bind) : (0.78f + 0.18f * bind);
        g_vm[b] = um ? (0.45f + 0.35f * im) : (0.75f + 0.20f * im);
        sh_tgt = tgt;
        sh_owt = owt;
        sh_bf = 0.5f + 0.5f * im;
    }
    __syncthreads();

    float ow = (n == sh_tgt) ? sh_owt : 0.0f;
    out[O9_ + idx] = ow;
    float up = clip01(wp * 0.98f + ow * sh_bf);
    out[O2_ + idx] = up;

    float s = up;
#pragma unroll
    for (int o = 16; o; o >>= 1) s += __shfl_xor_sync(0xffffffffu, s, o);
    __shared__ float ss4[4];
    if ((n & 31) == 0) ss4[n >> 5] = s;
    __syncthreads();
    if (n == 0) out[O7_ + b] = (ss4[0] + ss4[1] + ss4[2] + ss4[3]) * (1.0f / N_);
}

// =====================================================================
// Kernel 5: fix up the single target row per batch in both big outputs.
// grid B, block 128 (float4 per thread).
// =====================================================================
__global__ void __launch_bounds__(128) k_fixup(
    const float* __restrict__ wkeys, const float* __restrict__ wvals,
    float* __restrict__ out)
{
    const int b = blockIdx.x;
    const int i = threadIdx.x;
    const int t = g_tgt[b];
    const float ak = g_owt[b] * g_km[b];
    const float av = g_owt[b] * g_vm[b];
    const size_t roff = ((size_t)b * N_ + t) * D_;

    float4 k = reinterpret_cast<const float4*>(wkeys + roff)[i];
    float4 c = reinterpret_cast<const float4*>(g_ck + (size_t)b * D_)[i];
    float4 ok;
    ok.x = k.x + ak * (c.x - k.x);
    ok.y = k.y + ak * (c.y - k.y);
    ok.z = k.z + ak * (c.z - k.z);
    ok.w = k.w + ak * (c.w - k.w);
    reinterpret_cast<float4*>(out + roff)[i] = ok;

    float4 v = reinterpret_cast<const float4*>(wvals + roff)[i];
    float4 cv = reinterpret_cast<const float4*>(g_cv + (size_t)b * D_)[i];
    float4 ov;
    ov.x = v.x + av * (cv.x - v.x);
    ov.y = v.y + av * (cv.y - v.y);
    ov.z = v.z + av * (cv.z - v.z);
    ov.w = v.w + av * (cv.w - v.w);
    reinterpret_cast<float4*>(out + O1_ + roff)[i] = ov;
}

// =====================================================================
extern "C" void kernel_launch(void* const* d_in, const int* in_sizes, int n_in,
                              void* d_out, int out_size)
{
    const float* hidden = (const float*)d_in[0];
    const float* wkeys  = (const float*)d_in[1];
    const float* wvals  = (const float*)d_in[2];
    const float* wprot  = (const float*)d_in[3];
    const float* wusage = (const float*)d_in[4];
    const float* wage   = (const float*)d_in[5];
    const float* Wk  = (const float*)d_in[6];
    const float* bk  = (const float*)d_in[7];
    const float* Wv  = (const float*)d_in[8];
    const float* bv  = (const float*)d_in[9];
    const float* Wwr = (const float*)d_in[10];
    const float* bwr = (const float*)d_in[11];
    const float* Wmg = (const float*)d_in[12];
    const float* bmg = (const float*)d_in[13];
    const float* Wbd = (const float*)d_in[14];
    const float* bbd = (const float*)d_in[15];
    const float* Wim = (const float*)d_in[16];
    const float* bim = (const float*)d_in[17];
    const float* Woc = (const float*)d_in[18];
    const float* boc = (const float*)d_in[19];
    const float* Wpr = (const float*)d_in[20];
    const float* bpr = (const float*)d_in[21];
    float* out = (float*)d_out;

    k_gemm<<<dim3(B_ / 8, 2), 128>>>(hidden, Wk, bk, Wv, bv);
    k_heads<<<B_, 128>>>(hidden, Wwr, bwr, Wmg, bmg, Wbd, bbd, Wim, bim, out);
    k_score<<<B_ * N_, 256>>>(wkeys, wvals, Woc, boc, Wpr, bpr, out);
    k_select<<<B_, 128>>>(wprot, wusage, wage, out);
    k_fixup<<<B_, 128>>>(wkeys, wvals, out);
}

// round 2
// speedup vs baseline: 1.1643x; 1.1643x over previous
#include <cuda_runtime.h>
#include <math.h>

#define B_ 1024
#define N_ 128
#define D_ 512

// ---- output layout (float32, concatenated in reference return order) ----
__device__ __host__ constexpr size_t KD_ = (size_t)B_ * N_ * D_;   // 67108864
__device__ __host__ constexpr size_t O1_ = KD_;                    // updated_values
__device__ __host__ constexpr size_t O2_ = 2 * KD_;                // updated_protection (B*N)
__device__ __host__ constexpr size_t O3_ = O2_ + (size_t)B_ * N_;  // write_strength (B)
__device__ __host__ constexpr size_t O4_ = O3_ + B_;               // merge_preference (B)
__device__ __host__ constexpr size_t O5_ = O4_ + B_;               // binding_strength (B)
__device__ __host__ constexpr size_t O6_ = O5_ + B_;               // overwrite.mean (B)
__device__ __host__ constexpr size_t O7_ = O6_ + B_;               // updated_protection.mean (B)
__device__ __host__ constexpr size_t O8_ = O7_ + B_;               // max_similarity (B)
__device__ __host__ constexpr size_t O9_ = O8_ + B_;               // overwrite (B*N)

// ---- scratch (__device__ globals; no allocations allowed) ----
__device__ float g_ck[B_ * D_];     // candidate_key (tanh)
__device__ float g_cv[B_ * D_];     // candidate_value (tanh)
__device__ float g_sim[B_ * N_];
__device__ float g_occ[B_ * N_];
__device__ float g_lprot[B_ * N_];
__device__ float g_ws[B_];
__device__ float g_im[B_];
__device__ float g_hmg[B_];
__device__ float g_hbd[B_];
__device__ float g_invnc[B_];
__device__ int   g_tgt[B_];
__device__ float g_owt[B_];
__device__ float g_km[B_];
__device__ float g_vm[B_];

__device__ __forceinline__ float sigm(float x) { return 1.0f / (1.0f + expf(-x)); }
__device__ __forceinline__ float clip01(float x) { return fminf(fmaxf(x, 0.0f), 1.0f); }
__device__ __forceinline__ float dot4(float4 a, float4 b) {
    return a.x * b.x + a.y * b.y + a.z * b.z + a.w * b.w;
}

// =====================================================================
// Kernel 1: candidate key/value GEMM + tanh.
// grid (B/8, 2), block 128. Each block: 8 batches x 512 cols.
// =====================================================================
__global__ void __launch_bounds__(128) k_gemm(
    const float* __restrict__ hidden,
    const float* __restrict__ Wk, const float* __restrict__ bk,
    const float* __restrict__ Wv, const float* __restrict__ bv)
{
    __shared__ __align__(16) float ht[D_][12];  // transposed hidden tile, padded rows

    const int tid = threadIdx.x;
    const int b0 = blockIdx.x * 8;
    const float* __restrict__ W    = blockIdx.y ? Wv : Wk;
    const float* __restrict__ bias = blockIdx.y ? bv : bk;
    float* outp = blockIdx.y ? g_cv : g_ck;

    for (int i = tid; i < 8 * 128; i += 128) {
        int bb = i >> 7;
        int d4 = i & 127;
        float4 v = reinterpret_cast<const float4*>(hidden + (size_t)(b0 + bb) * D_)[d4];
        ht[4 * d4 + 0][bb] = v.x;
        ht[4 * d4 + 1][bb] = v.y;
        ht[4 * d4 + 2][bb] = v.z;
        ht[4 * d4 + 3][bb] = v.w;
    }
    __syncthreads();

    float acc[8][4];
#pragma unroll
    for (int i = 0; i < 8; i++)
#pragma unroll
        for (int j = 0; j < 4; j++) acc[i][j] = 0.0f;

#pragma unroll 4
    for (int d = 0; d < D_; d++) {
        const float* wr = W + (size_t)d * D_;
        float w0 = __ldg(wr + tid);
        float w1 = __ldg(wr + tid + 128);
        float w2 = __ldg(wr + tid + 256);
        float w3 = __ldg(wr + tid + 384);
        float4 ha = *reinterpret_cast<const float4*>(&ht[d][0]);
        float4 hb = *reinterpret_cast<const float4*>(&ht[d][4]);
        float h[8] = {ha.x, ha.y, ha.z, ha.w, hb.x, hb.y, hb.z, hb.w};
#pragma unroll
        for (int bb = 0; bb < 8; bb++) {
            acc[bb][0] += h[bb] * w0;
            acc[bb][1] += h[bb] * w1;
            acc[bb][2] += h[bb] * w2;
            acc[bb][3] += h[bb] * w3;
        }
    }

    float b0v = bias[tid];
    float b1v = bias[tid + 128];
    float b2v = bias[tid + 256];
    float b3v = bias[tid + 384];
#pragma unroll
    for (int bb = 0; bb < 8; bb++) {
        float* orow = outp + (size_t)(b0 + bb) * D_;
        orow[tid]       = tanhf(acc[bb][0] + b0v);
        orow[tid + 128] = tanhf(acc[bb][1] + b1v);
        orow[tid + 256] = tanhf(acc[bb][2] + b2v);
        orow[tid + 384] = tanhf(acc[bb][3] + b3v);
    }
}

// =====================================================================
// Kernel 2: per-batch scalar heads + ||candidate_key||.
// grid B, block 128 (float4 per thread).
// =====================================================================
__global__ void __launch_bounds__(128) k_heads(
    const float* __restrict__ hidden,
    const float* __restrict__ Wwr, const float* __restrict__ bwr,
    const float* __restrict__ Wmg, const float* __restrict__ bmg,
    const float* __restrict__ Wbd, const float* __restrict__ bbd,
    const float* __restrict__ Wim, const float* __restrict__ bim,
    float* __restrict__ out)
{
    const int b = blockIdx.x;
    const int t = threadIdx.x;
    float4 h = reinterpret_cast<const float4*>(hidden + (size_t)b * D_)[t];
    float4 c = reinterpret_cast<const float4*>(g_ck + (size_t)b * D_)[t];

    float4 w;
    w = reinterpret_cast<const float4*>(Wwr)[t];
    float pwr = dot4(h, w);
    w = reinterpret_cast<const float4*>(Wmg)[t];
    float pmg = dot4(h, w);
    w = reinterpret_cast<const float4*>(Wbd)[t];
    float pbd = dot4(h, w);
    w = reinterpret_cast<const float4*>(Wim)[t];
    float pim = dot4(h, w);
    float pss = dot4(c, c);

#pragma unroll
    for (int o = 16; o; o >>= 1) {
        pwr += __shfl_xor_sync(0xffffffffu, pwr, o);
        pmg += __shfl_xor_sync(0xffffffffu, pmg, o);
        pbd += __shfl_xor_sync(0xffffffffu, pbd, o);
        pim += __shfl_xor_sync(0xffffffffu, pim, o);
        pss += __shfl_xor_sync(0xffffffffu, pss, o);
    }
    __shared__ float red[4][5];
    if ((t & 31) == 0) {
        int wi = t >> 5;
        red[wi][0] = pwr; red[wi][1] = pmg; red[wi][2] = pbd;
        red[wi][3] = pim; red[wi][4] = pss;
    }
    __syncthreads();
    if (t == 0) {
        float dwr = red[0][0] + red[1][0] + red[2][0] + red[3][0];
        float dmg = red[0][1] + red[1][1] + red[2][1] + red[3][1];
        float dbd = red[0][2] + red[1][2] + red[2][2] + red[3][2];
        float dIm = red[0][3] + red[1][3] + red[2][3] + red[3][3];
        float dss = red[0][4] + red[1][4] + red[2][4] + red[3][4];
        float ws = sigm(dwr + bwr[0]);
        g_ws[b] = ws;
        out[O3_ + b] = ws;
        g_im[b] = sigm(dIm + bim[0]);
        g_hmg[b] = dmg + bmg[0];
        g_hbd[b] = dbd + bbd[0];
        g_invnc[b] = 1.0f / fmaxf(sqrtf(dss), 1e-6f);
    }
}

// =====================================================================
// Kernel 3: streaming pass, one WARP per row, no smem, no block sync.
// Warps [0, B*N)       : key row  -> sim, copy to out
// Warps [B*N, 2*B*N)   : val row  -> occ, lprot, copy to out
// Each thread: 4 front-batched float4 loads from the streamed row.
// =====================================================================
__global__ void __launch_bounds__(256) k_score(
    const float* __restrict__ wkeys, const float* __restrict__ wvals,
    const float* __restrict__ Woc, const float* __restrict__ boc,
    const float* __restrict__ Wpr, const float* __restrict__ bpr,
    float* __restrict__ out)
{
    const int warp = blockIdx.x * 8 + (threadIdx.x >> 5);
    const int lane = threadIdx.x & 31;

    if (warp < B_ * N_) {
        // ---- key row ----
        const int row = warp;
        const int b = row >> 7;
        const size_t rowoff = (size_t)row * D_;
        const float4* kr = reinterpret_cast<const float4*>(wkeys + rowoff);
        const float4* cr = reinterpret_cast<const float4*>(g_ck + (size_t)b * D_);
        float4* orow = reinterpret_cast<float4*>(out + rowoff);

        float4 k0 = kr[lane];
        float4 k1 = kr[lane + 32];
        float4 k2 = kr[lane + 64];
        float4 k3 = kr[lane + 96];
        float4 c0 = cr[lane];
        float4 c1 = cr[lane + 32];
        float4 c2 = cr[lane + 64];
        float4 c3 = cr[lane + 96];

        orow[lane]      = k0;
        orow[lane + 32] = k1;
        orow[lane + 64] = k2;
        orow[lane + 96] = k3;

        float p0 = dot4(k0, c0) + dot4(k1, c1) + dot4(k2, c2) + dot4(k3, c3);
        float p1 = dot4(k0, k0) + dot4(k1, k1) + dot4(k2, k2) + dot4(k3, k3);
#pragma unroll
        for (int o = 16; o; o >>= 1) {
            p0 += __shfl_xor_sync(0xffffffffu, p0, o);
            p1 += __shfl_xor_sync(0xffffffffu, p1, o);
        }
        if (lane == 0) {
            g_sim[row] = p0 * g_invnc[b] / fmaxf(sqrtf(p1), 1e-6f);
        }
    } else {
        // ---- value row ----
        const int row = warp - B_ * N_;
        const size_t rowoff = (size_t)row * D_;
        const float4* vr = reinterpret_cast<const float4*>(wvals + rowoff);
        const float4* wo = reinterpret_cast<const float4*>(Woc);
        const float4* wp = reinterpret_cast<const float4*>(Wpr);
        float4* orow = reinterpret_cast<float4*>(out + O1_ + rowoff);

        float4 v0 = vr[lane];
        float4 v1 = vr[lane + 32];
        float4 v2 = vr[lane + 64];
        float4 v3 = vr[lane + 96];
        float4 a0 = wo[lane];
        float4 a1 = wo[lane + 32];
        float4 a2 = wo[lane + 64];
        float4 a3 = wo[lane + 96];
        float4 b0 = wp[lane];
        float4 b1 = wp[lane + 32];
        float4 b2 = wp[lane + 64];
        float4 b3 = wp[lane + 96];

        orow[lane]      = v0;
        orow[lane + 32] = v1;
        orow[lane + 64] = v2;
        orow[lane + 96] = v3;

        float p0 = dot4(v0, v0) + dot4(v1, v1) + dot4(v2, v2) + dot4(v3, v3);
        float p1 = dot4(v0, a0) + dot4(v1, a1) + dot4(v2, a2) + dot4(v3, a3);
        float p2 = dot4(v0, b0) + dot4(v1, b1) + dot4(v2, b2) + dot4(v3, b3);
#pragma unroll
        for (int o = 16; o; o >>= 1) {
            p0 += __shfl_xor_sync(0xffffffffu, p0, o);
            p1 += __shfl_xor_sync(0xffffffffu, p1, o);
            p2 += __shfl_xor_sync(0xffffffffu, p2, o);
        }
        if (lane == 0) {
            float nocc = clip01(sqrtf(p0) * 0.04419417382415922f);  // / sqrt(512)
            float locc = sigm(p1 + __ldg(boc));
            g_occ[row] = clip01(0.5f * locc + 0.5f * nocc);
            g_lprot[row] = sigm(p2 + __ldg(bpr));
        }
    }
}

// =====================================================================
// Kernel 4: per-batch selection + all small outputs.
// grid B, block 128 (one thread per slot n).
// =====================================================================
__global__ void __launch_bounds__(128) k_select(
    const float* __restrict__ wprot, const float* __restrict__ wusage,
    const float* __restrict__ wage, float* __restrict__ out)
{
    const int b = blockIdx.x;
    const int n = threadIdx.x;
    const int idx = b * N_ + n;

    float sim = g_sim[idx];
    float occ = g_occ[idx];
    float lp  = g_lprot[idx];
    float wp  = wprot[idx];
    float ep = clip01(0.4f * lp + 0.6f * wp);
    float eu = clip01(0.5f * occ + 0.5f * wusage[idx]);
    float ea = clip01(wage[idx]);
    float rs = 1.15f * (1.0f - occ) + 0.85f * (1.0f - ep) + 0.65f * ea
             + 0.45f * (1.0f - eu) + 0.25f * (1.0f - sim);

    __shared__ float sS[N_], sO[N_], sU[N_], sA[N_], sE[N_];
    sS[n] = sim; sO[n] = occ; sU[n] = eu; sA[n] = ea; sE[n] = ep;

    // two argmaxes (first-index tie break, matching jnp.argmax)
    float v1 = sim; int i1 = n;
    float v2 = rs;  int i2 = n;
#pragma unroll
    for (int o = 16; o; o >>= 1) {
        float ov = __shfl_down_sync(0xffffffffu, v1, o);
        int   oi = __shfl_down_sync(0xffffffffu, i1, o);
        if (ov > v1 || (ov == v1 && oi < i1)) { v1 = ov; i1 = oi; }
        ov = __shfl_down_sync(0xffffffffu, v2, o);
        oi = __shfl_down_sync(0xffffffffu, i2, o);
        if (ov > v2 || (ov == v2 && oi < i2)) { v2 = ov; i2 = oi; }
    }
    __shared__ float wv1[4], wv2[4];
    __shared__ int wi1[4], wi2[4];
    if ((n & 31) == 0) {
        int w = n >> 5;
        wv1[w] = v1; wi1[w] = i1; wv2[w] = v2; wi2[w] = i2;
    }
    __syncthreads();

    __shared__ int sh_tgt;
    __shared__ float sh_owt, sh_bf;
    if (n == 0) {
        float bv = wv1[0]; int bi = wi1[0];
#pragma unroll
        for (int w = 1; w < 4; w++)
            if (wv1[w] > bv || (wv1[w] == bv && wi1[w] < bi)) { bv = wv1[w]; bi = wi1[w]; }
        int mi = bi;
        float rbv = wv2[0]; int ri = wi2[0];
#pragma unroll
        for (int w = 1; w < 4; w++)
            if (wv2[w] > rbv || (wv2[w] == rbv && wi2[w] < ri)) { rbv = wv2[w]; ri = wi2[w]; }

        float ms = sS[mi], mo = sO[mi], mu = sU[mi], ma = sA[mi];
        float mp = sigm(g_hmg[b] + 2.4f * ms + 1.6f * (mo - 0.5f)
                        + 1.0f * (mu - 0.5f) - 0.8f * ma);
        bool um = (mp >= 0.5f) && (ms > 0.55f) && (mo > 0.35f);
        int tgt = um ? mi : ri;
        float bind = sigm(g_hbd[b] + 2.2f * ms);
        float conflict = clip01(1.0f - sS[tgt]);
        float owt = (0.15f + 0.85f * g_ws[b]) * (1.0f - 0.65f * sE[tgt] * conflict);
        float im = g_im[b];

        out[O4_ + b] = mp;
        out[O5_ + b] = bind;
        out[O6_ + b] = owt * (1.0f / N_);
        out[O8_ + b] = ms;
        g_tgt[b] = tgt;
        g_owt[b] = owt;
        g_km[b] = um ? (0.22f + 0.38f * bind) : (0.78f + 0.18f * bind);
        g_vm[b] = um ? (0.45f + 0.35f * im) : (0.75f + 0.20f * im);
        sh_tgt = tgt;
        sh_owt = owt;
        sh_bf = 0.5f + 0.5f * im;
    }
    __syncthreads();

    float ow = (n == sh_tgt) ? sh_owt : 0.0f;
    out[O9_ + idx] = ow;
    float up = clip01(wp * 0.98f + ow * sh_bf);
    out[O2_ + idx] = up;

    float s = up;
#pragma unroll
    for (int o = 16; o; o >>= 1) s += __shfl_xor_sync(0xffffffffu, s, o);
    __shared__ float ss4[4];
    if ((n & 31) == 0) ss4[n >> 5] = s;
    __syncthreads();
    if (n == 0) out[O7_ + b] = (ss4[0] + ss4[1] + ss4[2] + ss4[3]) * (1.0f / N_);
}

// =====================================================================
// Kernel 5: fix up the single target row per batch in both big outputs.
// grid B, block 128 (float4 per thread).
// =====================================================================
__global__ void __launch_bounds__(128) k_fixup(
    const float* __restrict__ wkeys, const float* __restrict__ wvals,
    float* __restrict__ out)
{
    const int b = blockIdx.x;
    const int i = threadIdx.x;
    const int t = g_tgt[b];
    const float ak = g_owt[b] * g_km[b];
    const float av = g_owt[b] * g_vm[b];
    const size_t roff = ((size_t)b * N_ + t) * D_;

    float4 k = reinterpret_cast<const float4*>(wkeys + roff)[i];
    float4 c = reinterpret_cast<const float4*>(g_ck + (size_t)b * D_)[i];
    float4 ok;
    ok.x = k.x + ak * (c.x - k.x);
    ok.y = k.y + ak * (c.y - k.y);
    ok.z = k.z + ak * (c.z - k.z);
    ok.w = k.w + ak * (c.w - k.w);
    reinterpret_cast<float4*>(out + roff)[i] = ok;

    float4 v = reinterpret_cast<const float4*>(wvals + roff)[i];
    float4 cv = reinterpret_cast<const float4*>(g_cv + (size_t)b * D_)[i];
    float4 ov;
    ov.x = v.x + av * (cv.x - v.x);
    ov.y = v.y + av * (cv.y - v.y);
    ov.z = v.z + av * (cv.z - v.z);
    ov.w = v.w + av * (cv.w - v.w);
    reinterpret_cast<float4*>(out + O1_ + roff)[i] = ov;
}

// =====================================================================
extern "C" void kernel_launch(void* const* d_in, const int* in_sizes, int n_in,
                              void* d_out, int out_size)
{
    const float* hidden = (const float*)d_in[0];
    const float* wkeys  = (const float*)d_in[1];
    const float* wvals  = (const float*)d_in[2];
    const float* wprot  = (const float*)d_in[3];
    const float* wusage = (const float*)d_in[4];
    const float* wage   = (const float*)d_in[5];
    const float* Wk  = (const float*)d_in[6];
    const float* bk  = (const float*)d_in[7];
    const float* Wv  = (const float*)d_in[8];
    const float* bv  = (const float*)d_in[9];
    const float* Wwr = (const float*)d_in[10];
    const float* bwr = (const float*)d_in[11];
    const float* Wmg = (const float*)d_in[12];
    const float* bmg = (const float*)d_in[13];
    const float* Wbd = (const float*)d_in[14];
    const float* bbd = (const float*)d_in[15];
    const float* Wim = (const float*)d_in[16];
    const float* bim = (const float*)d_in[17];
    const float* Woc = (const float*)d_in[18];
    const float* boc = (const float*)d_in[19];
    const float* Wpr = (const float*)d_in[20];
    const float* bpr = (const float*)d_in[21];
    float* out = (float*)d_out;

    k_gemm<<<dim3(B_ / 8, 2), 128>>>(hidden, Wk, bk, Wv, bv);
    k_heads<<<B_, 128>>>(hidden, Wwr, bwr, Wmg, bmg, Wbd, bbd, Wim, bim, out);
    k_score<<<(2 * B_ * N_) / 8, 256>>>(wkeys, wvals, Woc, boc, Wpr, bpr, out);
    k_select<<<B_, 128>>>(wprot, wusage, wage, out);
    k_fixup<<<B_, 128>>>(wkeys, wvals, out);
}